// round 1
// baseline (speedup 1.0000x reference)
#include <cuda_runtime.h>
#include <math.h>

// ---------------- problem dims ----------------
#define BB    4
#define MM    8
#define NPTS  4096
#define PDD   256
#define VDD   256
#define HH    256
#define FDD   512
#define SS    128
#define BNP   (BB*NPTS)          // 16384 point rows
#define NSEG  (BB*SS)            // 512 segments

// ---------------- scratch (device globals; no allocation allowed) ----------------
__device__ float g_pp[BNP*HH];          // point proj, post LN+relu
__device__ float g_attn[BB*MM*NPTS];    // sigmoid attention, layout (b*M+m)*NP+p
__device__ float g_fmean[NSEG*HH];      // per-segment mean feature
__device__ float g_amean[NSEG*MM];      // per-segment mean attention (8 views)
__device__ float g_weighted[BNP*VDD];   // attention-weighted view features
__device__ float g_wvp[BNP*HH];         // weighted view proj, post LN+relu

// =====================================================================
// Generic fused GEMM + bias + LayerNorm (+ optional ReLU)
// out[row][0:NC] = act(LN(concat(X0[row],X1[row]) @ W + bias))
// W is [(K0+K1)][NC] row-major. 256 threads; thread owns NC/256 columns.
// =====================================================================
template<int K0, int K1, int NC, int TR, int KT, bool RELU>
__global__ __launch_bounds__(256) void gemm_ln_k(
    const float* __restrict__ X0, const float* __restrict__ X1,
    const float* __restrict__ W,  const float* __restrict__ bias,
    const float* __restrict__ gamma, const float* __restrict__ beta,
    float* __restrict__ out)
{
    constexpr int CPT = NC / 256;
    __shared__ float Wt[KT][NC];
    __shared__ float Xt[TR][KT];
    __shared__ float buf[TR][NC];
    __shared__ float smu[TR], srs[TR];

    const int tid = threadIdx.x;
    const long row0 = (long)blockIdx.x * TR;

    float acc[TR][CPT];
#pragma unroll
    for (int r = 0; r < TR; ++r)
#pragma unroll
        for (int c = 0; c < CPT; ++c) acc[r][c] = 0.f;

    const float* Xsrc[2] = {X0, X1};
    const int    Ksz[2]  = {K0, K1};
    int wbase = 0;
    for (int ph = 0; ph < 2; ++ph) {
        const float* X = Xsrc[ph];
        const int KK = Ksz[ph];
        for (int k0 = 0; k0 < KK; k0 += KT) {
            for (int i = tid; i < KT * NC; i += 256) {
                int kk = i / NC, j = i % NC;
                Wt[kk][j] = W[(size_t)(wbase + k0 + kk) * NC + j];
            }
            for (int i = tid; i < TR * KT; i += 256) {
                int r = i / KT, kk = i % KT;
                Xt[r][kk] = X[(size_t)(row0 + r) * KK + k0 + kk];
            }
            __syncthreads();
#pragma unroll
            for (int kk = 0; kk < KT; ++kk) {
                float w[CPT];
#pragma unroll
                for (int c = 0; c < CPT; ++c) w[c] = Wt[kk][tid + 256 * c];
#pragma unroll
                for (int r = 0; r < TR; ++r) {
                    float x = Xt[r][kk];
#pragma unroll
                    for (int c = 0; c < CPT; ++c) acc[r][c] = fmaf(x, w[c], acc[r][c]);
                }
            }
            __syncthreads();
        }
        wbase += KK;
    }

    // bias -> buf
#pragma unroll
    for (int c = 0; c < CPT; ++c) {
        float bv = bias[tid + 256 * c];
#pragma unroll
        for (int r = 0; r < TR; ++r) buf[r][tid + 256 * c] = acc[r][c] + bv;
    }
    __syncthreads();

    // LN stats (warp per rows)
    const int wid = tid >> 5, lane = tid & 31;
    for (int r = wid; r < TR; r += 8) {
        float s = 0.f, sq = 0.f;
        for (int j = lane; j < NC; j += 32) { float v = buf[r][j]; s += v; sq += v * v; }
#pragma unroll
        for (int o = 16; o > 0; o >>= 1) {
            s  += __shfl_xor_sync(0xffffffffu, s,  o);
            sq += __shfl_xor_sync(0xffffffffu, sq, o);
        }
        if (lane == 0) {
            float mu  = s / (float)NC;
            float var = sq / (float)NC - mu * mu;
            smu[r] = mu; srs[r] = rsqrtf(var + 1e-5f);
        }
    }
    __syncthreads();

    // apply LN (+ReLU), write out
#pragma unroll
    for (int c = 0; c < CPT; ++c) {
        int j = tid + 256 * c;
        float gv = gamma[j], bev = beta[j];
#pragma unroll
        for (int r = 0; r < TR; ++r) {
            float v = (buf[r][j] - smu[r]) * srs[r] * gv + bev;
            if (RELU) v = fmaxf(v, 0.f);
            out[(size_t)(row0 + r) * NC + j] = v;
        }
    }
}

// =====================================================================
// Fused attention path: per (b,m) and 16-point tile:
//   vp = relu(LN(vf @ vW + vb))                 (K=256)
//   h  = relu(LN([pp, vp] @ a1W + a1b))         (K=512, pp from gmem, vp from smem)
//   attn = sigmoid(h . a2W + a2b)
// Never materializes vp/h to global memory.
// =====================================================================
__global__ __launch_bounds__(256) void attn_fused_k(
    const float* __restrict__ vf,  const float* __restrict__ pp_,
    const float* __restrict__ vW,  const float* __restrict__ vb,
    const float* __restrict__ vg,  const float* __restrict__ vbe,
    const float* __restrict__ a1W, const float* __restrict__ a1b,
    const float* __restrict__ ag,  const float* __restrict__ abe,
    const float* __restrict__ a2W, const float* __restrict__ a2b,
    float* __restrict__ attn)
{
    constexpr int TR = 16, KT = 8;
    __shared__ float Wt[KT][HH];
    __shared__ float Xt[TR][KT];
    __shared__ float vpb[TR][HH];
    __shared__ float hb[TR][HH];
    __shared__ float smu[TR], srs[TR];

    const int tid = threadIdx.x;
    const int bm  = blockIdx.y;          // b*M + m
    const int b   = bm / MM;
    const int p0  = blockIdx.x * TR;
    const int wid = tid >> 5, lane = tid & 31;

    float acc[TR];
#pragma unroll
    for (int r = 0; r < TR; ++r) acc[r] = 0.f;

    // ---- Stage A: vp ----
    const float* xrow = vf + ((size_t)bm * NPTS + p0) * VDD;
    for (int k0 = 0; k0 < VDD; k0 += KT) {
        for (int i = tid; i < KT * HH; i += 256) {
            int kk = i >> 8, j = i & 255;
            Wt[kk][j] = vW[(size_t)(k0 + kk) * HH + j];
        }
        for (int i = tid; i < TR * KT; i += 256) {
            int r = i / KT, kk = i % KT;
            Xt[r][kk] = xrow[(size_t)r * VDD + k0 + kk];
        }
        __syncthreads();
#pragma unroll
        for (int kk = 0; kk < KT; ++kk) {
            float w = Wt[kk][tid];
#pragma unroll
            for (int r = 0; r < TR; ++r) acc[r] = fmaf(Xt[r][kk], w, acc[r]);
        }
        __syncthreads();
    }
    {
        float bv = vb[tid];
#pragma unroll
        for (int r = 0; r < TR; ++r) vpb[r][tid] = acc[r] + bv;
    }
    __syncthreads();
    for (int r = wid; r < TR; r += 8) {
        float s = 0.f, sq = 0.f;
        for (int j = lane; j < HH; j += 32) { float v = vpb[r][j]; s += v; sq += v * v; }
#pragma unroll
        for (int o = 16; o > 0; o >>= 1) {
            s  += __shfl_xor_sync(0xffffffffu, s,  o);
            sq += __shfl_xor_sync(0xffffffffu, sq, o);
        }
        if (lane == 0) {
            float mu = s / (float)HH, var = sq / (float)HH - mu * mu;
            smu[r] = mu; srs[r] = rsqrtf(var + 1e-5f);
        }
    }
    __syncthreads();
    {
        float gv = vg[tid], bev = vbe[tid];
#pragma unroll
        for (int r = 0; r < TR; ++r) {
            float v = (vpb[r][tid] - smu[r]) * srs[r] * gv + bev;
            vpb[r][tid] = fmaxf(v, 0.f);
        }
    }
    __syncthreads();

    // ---- Stage B: h = [pp, vp] @ a1W ----
#pragma unroll
    for (int r = 0; r < TR; ++r) acc[r] = 0.f;
    const float* prow = pp_ + ((size_t)b * NPTS + p0) * HH;
    for (int k0 = 0; k0 < HH; k0 += KT) {          // first half: pp (global)
        for (int i = tid; i < KT * HH; i += 256) {
            int kk = i >> 8, j = i & 255;
            Wt[kk][j] = a1W[(size_t)(k0 + kk) * HH + j];
        }
        for (int i = tid; i < TR * KT; i += 256) {
            int r = i / KT, kk = i % KT;
            Xt[r][kk] = prow[(size_t)r * HH + k0 + kk];
        }
        __syncthreads();
#pragma unroll
        for (int kk = 0; kk < KT; ++kk) {
            float w = Wt[kk][tid];
#pragma unroll
            for (int r = 0; r < TR; ++r) acc[r] = fmaf(Xt[r][kk], w, acc[r]);
        }
        __syncthreads();
    }
    for (int k0 = 0; k0 < HH; k0 += KT) {          // second half: vp (smem)
        for (int i = tid; i < KT * HH; i += 256) {
            int kk = i >> 8, j = i & 255;
            Wt[kk][j] = a1W[(size_t)(HH + k0 + kk) * HH + j];
        }
        __syncthreads();
#pragma unroll
        for (int kk = 0; kk < KT; ++kk) {
            float w = Wt[kk][tid];
#pragma unroll
            for (int r = 0; r < TR; ++r) acc[r] = fmaf(vpb[r][k0 + kk], w, acc[r]);
        }
        __syncthreads();
    }
    {
        float bv = a1b[tid];
#pragma unroll
        for (int r = 0; r < TR; ++r) hb[r][tid] = acc[r] + bv;
    }
    __syncthreads();
    for (int r = wid; r < TR; r += 8) {
        float s = 0.f, sq = 0.f;
        for (int j = lane; j < HH; j += 32) { float v = hb[r][j]; s += v; sq += v * v; }
#pragma unroll
        for (int o = 16; o > 0; o >>= 1) {
            s  += __shfl_xor_sync(0xffffffffu, s,  o);
            sq += __shfl_xor_sync(0xffffffffu, sq, o);
        }
        if (lane == 0) {
            float mu = s / (float)HH, var = sq / (float)HH - mu * mu;
            smu[r] = mu; srs[r] = rsqrtf(var + 1e-5f);
        }
    }
    __syncthreads();
    {
        float gv = ag[tid], bev = abe[tid];
#pragma unroll
        for (int r = 0; r < TR; ++r) {
            float v = (hb[r][tid] - smu[r]) * srs[r] * gv + bev;
            hb[r][tid] = fmaxf(v, 0.f);
        }
    }
    __syncthreads();

    // ---- Stage C: attn = sigmoid(h . a2W + a2b) ----
    float b2 = a2b[0];
    for (int r = wid; r < TR; r += 8) {
        float d = 0.f;
        for (int j = lane; j < HH; j += 32) d = fmaf(hb[r][j], a2W[j], d);
#pragma unroll
        for (int o = 16; o > 0; o >>= 1) d += __shfl_xor_sync(0xffffffffu, d, o);
        if (lane == 0)
            attn[(size_t)bm * NPTS + p0 + r] = 1.f / (1.f + expf(-(d + b2)));
    }
}

// =====================================================================
// Segment means: one block per (b, s). Deterministic (no atomics).
// =====================================================================
__global__ __launch_bounds__(256) void seg_stats_k(
    const int* __restrict__ sp, const float* __restrict__ pp_,
    const float* __restrict__ attn,
    float* __restrict__ fmean, float* __restrict__ amean)
{
    __shared__ int sids[NPTS];
    const int b = blockIdx.x / SS, s = blockIdx.x % SS;
    const int tid = threadIdx.x;
    for (int i = tid; i < NPTS; i += 256) sids[i] = sp[b * NPTS + i];
    __syncthreads();

    float facc = 0.f, aacc = 0.f;
    int cnt = 0;
    for (int p = 0; p < NPTS; ++p) {
        if (sids[p] == s) {
            facc += pp_[((size_t)b * NPTS + p) * HH + tid];
            if (tid < MM) aacc += attn[((size_t)b * MM + tid) * NPTS + p];
            ++cnt;
        }
    }
    float inv = 1.f / (float)(cnt > 0 ? cnt : 1);
    fmean[(size_t)blockIdx.x * HH + tid] = facc * inv;
    if (tid < MM) amean[blockIdx.x * MM + tid] = aacc * inv;
}

// =====================================================================
// Refine + softmax(8 views) + weighted view-feature sum. One warp / point.
// =====================================================================
__global__ __launch_bounds__(256) void refine_weighted_k(
    const int* __restrict__ sp, const float* __restrict__ pp_,
    const float* __restrict__ attn, const float* __restrict__ vf,
    const float* __restrict__ fmean, const float* __restrict__ amean,
    float* __restrict__ weighted)
{
    const int wid = threadIdx.x >> 5, lane = threadIdx.x & 31;
    const int g = blockIdx.x * 8 + wid;           // global point row
    const int b = g / NPTS, p = g % NPTS;

    const int s = sp[g];
    float a[MM], rf[MM];
#pragma unroll
    for (int m = 0; m < MM; ++m) a[m] = attn[((size_t)b * MM + m) * NPTS + p];

    if (s >= 0) {
        const int seg = b * SS + s;
        const float* f  = pp_   + (size_t)g   * HH;
        const float* fm = fmean + (size_t)seg * HH;
        float dot = 0.f, nf = 0.f, nm = 0.f;
        for (int j = lane; j < HH; j += 32) {
            float x = f[j], y = fm[j];
            dot = fmaf(x, y, dot); nf = fmaf(x, x, nf); nm = fmaf(y, y, nm);
        }
#pragma unroll
        for (int o = 16; o > 0; o >>= 1) {
            dot += __shfl_xor_sync(0xffffffffu, dot, o);
            nf  += __shfl_xor_sync(0xffffffffu, nf,  o);
            nm  += __shfl_xor_sync(0xffffffffu, nm,  o);
        }
        float sim = dot / (fmaxf(sqrtf(nf), 1e-8f) * fmaxf(sqrtf(nm), 1e-8f));
#pragma unroll
        for (int m = 0; m < MM; ++m) {
            float am = amean[seg * MM + m];
            rf[m] = am + (a[m] - am) * sim;
        }
    } else {
#pragma unroll
        for (int m = 0; m < MM; ++m) rf[m] = a[m];
    }

    // softmax over the 8 views (all lanes redundantly)
    float mx = rf[0];
#pragma unroll
    for (int m = 1; m < MM; ++m) mx = fmaxf(mx, rf[m]);
    float w[MM], ssum = 0.f;
#pragma unroll
    for (int m = 0; m < MM; ++m) { w[m] = expf(rf[m] - mx); ssum += w[m]; }
    float inv = 1.f / ssum;
#pragma unroll
    for (int m = 0; m < MM; ++m) w[m] *= inv;

    // weighted = sum_m w[m] * vf[b,m,p,:]
#pragma unroll
    for (int c = 0; c < VDD / 32; ++c) {
        int d = lane + 32 * c;
        float accv = 0.f;
#pragma unroll
        for (int m = 0; m < MM; ++m)
            accv = fmaf(w[m], vf[(((size_t)b * MM + m) * NPTS + p) * VDD + d], accv);
        weighted[(size_t)g * VDD + d] = accv;
    }
}

// =====================================================================
// Launch
// =====================================================================
extern "C" void kernel_launch(void* const* d_in, const int* in_sizes, int n_in,
                              void* d_out, int out_size)
{
    (void)in_sizes; (void)n_in; (void)out_size;
    const float* pf   = (const float*)d_in[0];
    const float* vf   = (const float*)d_in[1];
    const int*   spid = (const int*)  d_in[2];
    const float* pW  = (const float*)d_in[3];
    const float* pb  = (const float*)d_in[4];
    const float* pg  = (const float*)d_in[5];
    const float* pbe = (const float*)d_in[6];
    const float* vW  = (const float*)d_in[7];
    const float* vb  = (const float*)d_in[8];
    const float* vg  = (const float*)d_in[9];
    const float* vbe = (const float*)d_in[10];
    const float* a1W = (const float*)d_in[11];
    const float* a1b = (const float*)d_in[12];
    const float* ag  = (const float*)d_in[13];
    const float* abe = (const float*)d_in[14];
    const float* a2W = (const float*)d_in[15];
    const float* a2b = (const float*)d_in[16];
    const float* fW  = (const float*)d_in[17];
    const float* fb  = (const float*)d_in[18];
    const float* fg  = (const float*)d_in[19];
    const float* fbe = (const float*)d_in[20];

    float *pp, *attn, *fmean, *amean, *wtd, *wvp;
    cudaGetSymbolAddress((void**)&pp,    g_pp);
    cudaGetSymbolAddress((void**)&attn,  g_attn);
    cudaGetSymbolAddress((void**)&fmean, g_fmean);
    cudaGetSymbolAddress((void**)&amean, g_amean);
    cudaGetSymbolAddress((void**)&wtd,   g_weighted);
    cudaGetSymbolAddress((void**)&wvp,   g_wvp);

    // 1) pp = relu(LN(pf @ pW + pb))
    gemm_ln_k<PDD, 0, HH, 32, 8, true><<<BNP / 32, 256>>>(
        pf, nullptr, pW, pb, pg, pbe, pp);

    // 2) fused vp/h/attn
    attn_fused_k<<<dim3(NPTS / 16, BB * MM), 256>>>(
        vf, pp, vW, vb, vg, vbe, a1W, a1b, ag, abe, a2W, a2b, attn);

    // 3) segment means
    seg_stats_k<<<NSEG, 256>>>(spid, pp, attn, fmean, amean);

    // 4) refine + softmax + weighted view sum
    refine_weighted_k<<<BNP / 8, 256>>>(spid, pp, attn, vf, fmean, amean, wtd);

    // 5) wvp = relu(LN(weighted @ vW + vb))
    gemm_ln_k<VDD, 0, HH, 32, 8, true><<<BNP / 32, 256>>>(
        wtd, nullptr, vW, vb, vg, vbe, wvp);

    // 6) Z = LN([pp, wvp] @ fW + fb)
    gemm_ln_k<HH, HH, FDD, 16, 4, false><<<BNP / 16, 256>>>(
        pp, wvp, fW, fb, fg, fbe, (float*)d_out);
}

// round 3
// speedup vs baseline: 2.1191x; 2.1191x over previous
#include <cuda_runtime.h>
#include <math.h>

typedef unsigned long long ull;

// ---------------- problem dims ----------------
#define BB    4
#define MM    8
#define NPTS  4096
#define PDD   256
#define VDD   256
#define HH    256
#define FDD   512
#define SS    128
#define BNP   (BB*NPTS)          // 16384 point rows
#define NSEG  (BB*SS)            // 512 segments

// ---------------- scratch (device globals; no allocation allowed) ----------------
__device__ float g_pp[BNP*HH];          // point proj, post LN+relu
__device__ float g_attn[BB*MM*NPTS];    // sigmoid attention, layout (b*M+m)*NP+p
__device__ float g_fmean[NSEG*HH];      // per-segment mean feature
__device__ float g_amean[NSEG*MM];      // per-segment mean attention (8 views)
__device__ float g_weighted[BNP*VDD];   // attention-weighted view features
__device__ float g_wvp[BNP*HH];         // weighted view proj, post LN+relu

// ---------------- f32x2 packed helpers ----------------
__device__ __forceinline__ ull fpack(float a, float b) {
    ull r; asm("mov.b64 %0, {%1, %2};" : "=l"(r) : "f"(a), "f"(b)); return r;
}
__device__ __forceinline__ void funpack(ull v, float& a, float& b) {
    asm("mov.b64 {%0, %1}, %2;" : "=f"(a), "=f"(b) : "l"(v));
}
__device__ __forceinline__ void ffma2(ull& d, ull a, ull b) {
    asm("fma.rn.f32x2 %0, %1, %2, %0;" : "+l"(d) : "l"(a), "l"(b));
}

// =====================================================================
// Register-tiled GEMM + bias + LayerNorm (+ optional ReLU), f32x2 packed.
// out[row][0:NC] = act(LN(concat(X0[row],X1[row]) @ W + bias))
// W is [(K0+K1)][NC] row-major. 256 threads.
// Thread grid: COLT=NC/4 col-threads (4 contiguous cols each),
//              ROWT=256/COLT row-groups (RPT=TR/ROWT rows each).
// Row pairs packed into f32x2 lanes; W duplicated into both lanes.
// =====================================================================
template<int K0, int K1, int NC, int TR, int KT, bool RELU>
__global__ __launch_bounds__(256) void gemm_ln_k(
    const float* __restrict__ X0, const float* __restrict__ X1,
    const float* __restrict__ W,  const float* __restrict__ bias,
    const float* __restrict__ gamma, const float* __restrict__ beta,
    float* __restrict__ out)
{
    constexpr int COLT = NC / 4;
    constexpr int ROWT = 256 / COLT;
    constexpr int RPT  = TR / ROWT;
    constexpr int NP   = RPT / 2;
    constexpr int XS   = TR + 2;            // even pad: keeps 8B alignment

    extern __shared__ float sm[];
    float* Wt  = sm;                        // KT*NC
    float* Xt  = Wt + KT * NC;              // KT*XS (k-major, rows contiguous)
    float* buf = Xt + KT * XS;              // TR*NC
    float* smu = buf + TR * NC;             // TR
    float* srs = smu + TR;                  // TR

    const int tid = threadIdx.x;
    const int tx  = tid % COLT;
    const int ty  = tid / COLT;
    const size_t row0 = (size_t)blockIdx.x * TR;

    ull acc[NP][4];
#pragma unroll
    for (int p = 0; p < NP; ++p)
#pragma unroll
        for (int c = 0; c < 4; ++c) acc[p][c] = 0ull;

    const float* Xsrc[2] = {X0, X1};
    const int    Ksz[2]  = {K0, K1};
    int wbase = 0;
    for (int ph = 0; ph < 2; ++ph) {
        const float* X = Xsrc[ph];
        const int KK = Ksz[ph];
        for (int k0 = 0; k0 < KK; k0 += KT) {
            // stage W tile (vectorized)
            for (int i = tid; i < KT * NC / 4; i += 256) {
                int kk = i / (NC / 4), j = i % (NC / 4);
                *(float4*)(Wt + kk * NC + j * 4) =
                    *(const float4*)(W + (size_t)(wbase + k0 + kk) * NC + j * 4);
            }
            // stage X tile transposed: Xt[kk][r]
            for (int i = tid; i < TR * KT / 4; i += 256) {
                int r = i / (KT / 4), c = i % (KT / 4);
                float4 v = *(const float4*)(X + (row0 + r) * KK + k0 + c * 4);
                Xt[(c * 4 + 0) * XS + r] = v.x;
                Xt[(c * 4 + 1) * XS + r] = v.y;
                Xt[(c * 4 + 2) * XS + r] = v.z;
                Xt[(c * 4 + 3) * XS + r] = v.w;
            }
            __syncthreads();
#pragma unroll
            for (int kk = 0; kk < KT; ++kk) {
                ull xp[NP];
                const ull* xr = (const ull*)(Xt + kk * XS + ty * RPT);
#pragma unroll
                for (int p = 0; p < NP; ++p) xp[p] = xr[p];
                const float4 wv = *(const float4*)(Wt + kk * NC + tx * 4);
                ull wd[4];
                wd[0] = fpack(wv.x, wv.x); wd[1] = fpack(wv.y, wv.y);
                wd[2] = fpack(wv.z, wv.z); wd[3] = fpack(wv.w, wv.w);
#pragma unroll
                for (int p = 0; p < NP; ++p)
#pragma unroll
                    for (int c = 0; c < 4; ++c) ffma2(acc[p][c], xp[p], wd[c]);
            }
            __syncthreads();
        }
        wbase += KK;
    }

    // bias + unpack -> buf
    {
        const float4 bv = *(const float4*)(bias + tx * 4);
        const float bb[4] = {bv.x, bv.y, bv.z, bv.w};
#pragma unroll
        for (int p = 0; p < NP; ++p)
#pragma unroll
            for (int c = 0; c < 4; ++c) {
                float lo, hi; funpack(acc[p][c], lo, hi);
                int r = ty * RPT + 2 * p;
                buf[(size_t)r * NC + tx * 4 + c]       = lo + bb[c];
                buf[(size_t)(r + 1) * NC + tx * 4 + c] = hi + bb[c];
            }
    }
    __syncthreads();

    // LN stats: warp per rows
    const int wid = tid >> 5, lane = tid & 31;
    for (int r = wid; r < TR; r += 8) {
        float s = 0.f, sq = 0.f;
        for (int j = lane; j < NC; j += 32) { float v = buf[(size_t)r * NC + j]; s += v; sq += v * v; }
#pragma unroll
        for (int o = 16; o > 0; o >>= 1) {
            s  += __shfl_xor_sync(0xffffffffu, s,  o);
            sq += __shfl_xor_sync(0xffffffffu, sq, o);
        }
        if (lane == 0) {
            float mu  = s / (float)NC;
            float var = sq / (float)NC - mu * mu;
            smu[r] = mu; srs[r] = rsqrtf(var + 1e-5f);
        }
    }
    __syncthreads();

    // apply LN (+ReLU), write out (coalesced)
    constexpr int CPT = NC / 256;
#pragma unroll
    for (int c = 0; c < CPT; ++c) {
        int j = tid + 256 * c;
        float gv = gamma[j], bev = beta[j];
        for (int r = 0; r < TR; ++r) {
            float v = (buf[(size_t)r * NC + j] - smu[r]) * srs[r] * gv + bev;
            if (RELU) v = fmaxf(v, 0.f);
            out[(row0 + r) * NC + j] = v;
        }
    }
}

// =====================================================================
// Fused attention path (register-tiled, f32x2). Per (b,m), 64-point tile:
//   vp = relu(LN(vf @ vW + vb))                 (K=256)
//   h  = relu(LN([pp, vp] @ a1W + a1b))         (K=512; pp gmem, vp smem)
//   attn = sigmoid(h . a2W + a2b)               (LN+relu fused into dot)
// vp/h never touch global memory.
// =====================================================================
__global__ __launch_bounds__(256) void attn_fused_k(
    const float* __restrict__ vf,  const float* __restrict__ pp_,
    const float* __restrict__ vW,  const float* __restrict__ vb,
    const float* __restrict__ vg,  const float* __restrict__ vbe,
    const float* __restrict__ a1W, const float* __restrict__ a1b,
    const float* __restrict__ ag,  const float* __restrict__ abe,
    const float* __restrict__ a2W, const float* __restrict__ a2b,
    float* __restrict__ attn)
{
    constexpr int TR = 64, KT = 16, NC = HH;       // 256
    constexpr int COLT = NC / 4;                   // 64
    constexpr int ROWT = 256 / COLT;               // 4
    constexpr int RPT  = TR / ROWT;                // 16
    constexpr int NP   = RPT / 2;                  // 8
    constexpr int XS   = TR + 2;

    extern __shared__ float sm[];
    float* Wt   = sm;                              // KT*NC = 4096
    float* Xt   = Wt + KT * NC;                    // KT*XS = 1056
    float* sbuf = Xt + KT * XS;                    // TR*NC = 16384
    float* smu  = sbuf + TR * NC;
    float* srs  = smu + TR;

    const int tid = threadIdx.x;
    const int tx  = tid % COLT;
    const int ty  = tid / COLT;
    const int wid = tid >> 5, lane = tid & 31;
    const int bm  = blockIdx.y;                    // b*M + m
    const int b   = bm / MM;
    const size_t row0 = (size_t)blockIdx.x * TR;   // point tile base

    ull acc[NP][4];

    // ================= Stage A: vp = vf @ vW =================
#pragma unroll
    for (int p = 0; p < NP; ++p)
#pragma unroll
        for (int c = 0; c < 4; ++c) acc[p][c] = 0ull;

    const float* xbase = vf + ((size_t)bm * NPTS + row0) * VDD;
    for (int k0 = 0; k0 < VDD; k0 += KT) {
        for (int i = tid; i < KT * NC / 4; i += 256) {
            int kk = i / (NC / 4), j = i % (NC / 4);
            *(float4*)(Wt + kk * NC + j * 4) =
                *(const float4*)(vW + (size_t)(k0 + kk) * NC + j * 4);
        }
        {
            int i = tid;                            // TR*KT/4 == 256 exactly
            int r = i / (KT / 4), c = i % (KT / 4);
            float4 v = *(const float4*)(xbase + (size_t)r * VDD + k0 + c * 4);
            Xt[(c * 4 + 0) * XS + r] = v.x;
            Xt[(c * 4 + 1) * XS + r] = v.y;
            Xt[(c * 4 + 2) * XS + r] = v.z;
            Xt[(c * 4 + 3) * XS + r] = v.w;
        }
        __syncthreads();
#pragma unroll
        for (int kk = 0; kk < KT; ++kk) {
            ull xp[NP];
            const ull* xr = (const ull*)(Xt + kk * XS + ty * RPT);
#pragma unroll
            for (int p = 0; p < NP; ++p) xp[p] = xr[p];
            const float4 wv = *(const float4*)(Wt + kk * NC + tx * 4);
            ull wd[4];
            wd[0] = fpack(wv.x, wv.x); wd[1] = fpack(wv.y, wv.y);
            wd[2] = fpack(wv.z, wv.z); wd[3] = fpack(wv.w, wv.w);
#pragma unroll
            for (int p = 0; p < NP; ++p)
#pragma unroll
                for (int c = 0; c < 4; ++c) ffma2(acc[p][c], xp[p], wd[c]);
        }
        __syncthreads();
    }
    // epilogue A: bias -> sbuf, LN stats, normalize+relu in place
    {
        const float4 bv = *(const float4*)(vb + tx * 4);
        const float bb[4] = {bv.x, bv.y, bv.z, bv.w};
#pragma unroll
        for (int p = 0; p < NP; ++p)
#pragma unroll
            for (int c = 0; c < 4; ++c) {
                float lo, hi; funpack(acc[p][c], lo, hi);
                int r = ty * RPT + 2 * p;
                sbuf[(size_t)r * NC + tx * 4 + c]       = lo + bb[c];
                sbuf[(size_t)(r + 1) * NC + tx * 4 + c] = hi + bb[c];
            }
    }
    __syncthreads();
    for (int r = wid; r < TR; r += 8) {
        float s = 0.f, sq = 0.f;
        for (int j = lane; j < NC; j += 32) { float v = sbuf[(size_t)r * NC + j]; s += v; sq += v * v; }
#pragma unroll
        for (int o = 16; o > 0; o >>= 1) {
            s  += __shfl_xor_sync(0xffffffffu, s,  o);
            sq += __shfl_xor_sync(0xffffffffu, sq, o);
        }
        if (lane == 0) {
            float mu = s / (float)NC, var = sq / (float)NC - mu * mu;
            smu[r] = mu; srs[r] = rsqrtf(var + 1e-5f);
        }
    }
    __syncthreads();
    {
        float gv = vg[tid], bev = vbe[tid];
        for (int r = 0; r < TR; ++r) {
            float v = (sbuf[(size_t)r * NC + tid] - smu[r]) * srs[r] * gv + bev;
            sbuf[(size_t)r * NC + tid] = fmaxf(v, 0.f);
        }
    }
    __syncthreads();

    // ================= Stage B: h = [pp, vp] @ a1W =================
#pragma unroll
    for (int p = 0; p < NP; ++p)
#pragma unroll
        for (int c = 0; c < 4; ++c) acc[p][c] = 0ull;

    // phase 1: pp from gmem (K rows 0..255 of a1W)
    const float* prow = pp_ + ((size_t)b * NPTS + row0) * HH;
    for (int k0 = 0; k0 < HH; k0 += KT) {
        for (int i = tid; i < KT * NC / 4; i += 256) {
            int kk = i / (NC / 4), j = i % (NC / 4);
            *(float4*)(Wt + kk * NC + j * 4) =
                *(const float4*)(a1W + (size_t)(k0 + kk) * NC + j * 4);
        }
        {
            int i = tid;
            int r = i / (KT / 4), c = i % (KT / 4);
            float4 v = *(const float4*)(prow + (size_t)r * HH + k0 + c * 4);
            Xt[(c * 4 + 0) * XS + r] = v.x;
            Xt[(c * 4 + 1) * XS + r] = v.y;
            Xt[(c * 4 + 2) * XS + r] = v.z;
            Xt[(c * 4 + 3) * XS + r] = v.w;
        }
        __syncthreads();
#pragma unroll
        for (int kk = 0; kk < KT; ++kk) {
            ull xp[NP];
            const ull* xr = (const ull*)(Xt + kk * XS + ty * RPT);
#pragma unroll
            for (int p = 0; p < NP; ++p) xp[p] = xr[p];
            const float4 wv = *(const float4*)(Wt + kk * NC + tx * 4);
            ull wd[4];
            wd[0] = fpack(wv.x, wv.x); wd[1] = fpack(wv.y, wv.y);
            wd[2] = fpack(wv.z, wv.z); wd[3] = fpack(wv.w, wv.w);
#pragma unroll
            for (int p = 0; p < NP; ++p)
#pragma unroll
                for (int c = 0; c < 4; ++c) ffma2(acc[p][c], xp[p], wd[c]);
        }
        __syncthreads();
    }
    // phase 2: vp from smem (K rows 256..511 of a1W)
    for (int k0 = 0; k0 < HH; k0 += KT) {
        for (int i = tid; i < KT * NC / 4; i += 256) {
            int kk = i / (NC / 4), j = i % (NC / 4);
            *(float4*)(Wt + kk * NC + j * 4) =
                *(const float4*)(a1W + (size_t)(HH + k0 + kk) * NC + j * 4);
        }
        {
            int i = tid;
            int r = i / (KT / 4), c = i % (KT / 4);
            float4 v = *(const float4*)(sbuf + (size_t)r * NC + k0 + c * 4);
            Xt[(c * 4 + 0) * XS + r] = v.x;
            Xt[(c * 4 + 1) * XS + r] = v.y;
            Xt[(c * 4 + 2) * XS + r] = v.z;
            Xt[(c * 4 + 3) * XS + r] = v.w;
        }
        __syncthreads();
#pragma unroll
        for (int kk = 0; kk < KT; ++kk) {
            ull xp[NP];
            const ull* xr = (const ull*)(Xt + kk * XS + ty * RPT);
#pragma unroll
            for (int p = 0; p < NP; ++p) xp[p] = xr[p];
            const float4 wv = *(const float4*)(Wt + kk * NC + tx * 4);
            ull wd[4];
            wd[0] = fpack(wv.x, wv.x); wd[1] = fpack(wv.y, wv.y);
            wd[2] = fpack(wv.z, wv.z); wd[3] = fpack(wv.w, wv.w);
#pragma unroll
            for (int p = 0; p < NP; ++p)
#pragma unroll
                for (int c = 0; c < 4; ++c) ffma2(acc[p][c], xp[p], wd[c]);
        }
        __syncthreads();
    }
    // epilogue B: h (pre-LN) overwrites sbuf (all reads done, synced)
    {
        const float4 bv = *(const float4*)(a1b + tx * 4);
        const float bb[4] = {bv.x, bv.y, bv.z, bv.w};
#pragma unroll
        for (int p = 0; p < NP; ++p)
#pragma unroll
            for (int c = 0; c < 4; ++c) {
                float lo, hi; funpack(acc[p][c], lo, hi);
                int r = ty * RPT + 2 * p;
                sbuf[(size_t)r * NC + tx * 4 + c]       = lo + bb[c];
                sbuf[(size_t)(r + 1) * NC + tx * 4 + c] = hi + bb[c];
            }
    }
    __syncthreads();
    for (int r = wid; r < TR; r += 8) {
        float s = 0.f, sq = 0.f;
        for (int j = lane; j < NC; j += 32) { float v = sbuf[(size_t)r * NC + j]; s += v; sq += v * v; }
#pragma unroll
        for (int o = 16; o > 0; o >>= 1) {
            s  += __shfl_xor_sync(0xffffffffu, s,  o);
            sq += __shfl_xor_sync(0xffffffffu, sq, o);
        }
        if (lane == 0) {
            float mu = s / (float)NC, var = sq / (float)NC - mu * mu;
            smu[r] = mu; srs[r] = rsqrtf(var + 1e-5f);
        }
    }
    __syncthreads();

    // ================= Stage C: attn = sigmoid(relu(LN(h)) . a2W) ===
    {
        float b2 = a2b[0];
        for (int r = wid; r < TR; r += 8) {
            float mu = smu[r], rs = srs[r];
            float d = 0.f;
            for (int j = lane; j < NC; j += 32) {
                float v = (sbuf[(size_t)r * NC + j] - mu) * rs * ag[j] + abe[j];
                v = fmaxf(v, 0.f);
                d = fmaf(v, a2W[j], d);
            }
#pragma unroll
            for (int o = 16; o > 0; o >>= 1) d += __shfl_xor_sync(0xffffffffu, d, o);
            if (lane == 0)
                attn[(size_t)bm * NPTS + row0 + r] = 1.f / (1.f + expf(-(d + b2)));
        }
    }
}

// =====================================================================
// Segment means: one block per (b, s). Deterministic (no atomics).
// =====================================================================
__global__ __launch_bounds__(256) void seg_stats_k(
    const int* __restrict__ sp, const float* __restrict__ pp_,
    const float* __restrict__ attn,
    float* __restrict__ fmean, float* __restrict__ amean)
{
    __shared__ int sids[NPTS];
    const int b = blockIdx.x / SS, s = blockIdx.x % SS;
    const int tid = threadIdx.x;
    for (int i = tid; i < NPTS; i += 256) sids[i] = sp[b * NPTS + i];
    __syncthreads();

    float facc = 0.f, aacc = 0.f;
    int cnt = 0;
    for (int p = 0; p < NPTS; ++p) {
        if (sids[p] == s) {
            facc += pp_[((size_t)b * NPTS + p) * HH + tid];
            if (tid < MM) aacc += attn[((size_t)b * MM + tid) * NPTS + p];
            ++cnt;
        }
    }
    float inv = 1.f / (float)(cnt > 0 ? cnt : 1);
    fmean[(size_t)blockIdx.x * HH + tid] = facc * inv;
    if (tid < MM) amean[blockIdx.x * MM + tid] = aacc * inv;
}

// =====================================================================
// Refine + softmax(8 views) + weighted view-feature sum. One warp / point.
// =====================================================================
__global__ __launch_bounds__(256) void refine_weighted_k(
    const int* __restrict__ sp, const float* __restrict__ pp_,
    const float* __restrict__ attn, const float* __restrict__ vf,
    const float* __restrict__ fmean, const float* __restrict__ amean,
    float* __restrict__ weighted)
{
    const int wid = threadIdx.x >> 5, lane = threadIdx.x & 31;
    const int g = blockIdx.x * 8 + wid;           // global point row
    const int b = g / NPTS, p = g % NPTS;

    const int s = sp[g];
    float a[MM], rf[MM];
#pragma unroll
    for (int m = 0; m < MM; ++m) a[m] = attn[((size_t)b * MM + m) * NPTS + p];

    if (s >= 0) {
        const int seg = b * SS + s;
        const float* f  = pp_   + (size_t)g   * HH;
        const float* fm = fmean + (size_t)seg * HH;
        float dot = 0.f, nf = 0.f, nm = 0.f;
        for (int j = lane; j < HH; j += 32) {
            float x = f[j], y = fm[j];
            dot = fmaf(x, y, dot); nf = fmaf(x, x, nf); nm = fmaf(y, y, nm);
        }
#pragma unroll
        for (int o = 16; o > 0; o >>= 1) {
            dot += __shfl_xor_sync(0xffffffffu, dot, o);
            nf  += __shfl_xor_sync(0xffffffffu, nf,  o);
            nm  += __shfl_xor_sync(0xffffffffu, nm,  o);
        }
        float sim = dot / (fmaxf(sqrtf(nf), 1e-8f) * fmaxf(sqrtf(nm), 1e-8f));
#pragma unroll
        for (int m = 0; m < MM; ++m) {
            float am = amean[seg * MM + m];
            rf[m] = am + (a[m] - am) * sim;
        }
    } else {
#pragma unroll
        for (int m = 0; m < MM; ++m) rf[m] = a[m];
    }

    // softmax over the 8 views (all lanes redundantly)
    float mx = rf[0];
#pragma unroll
    for (int m = 1; m < MM; ++m) mx = fmaxf(mx, rf[m]);
    float w[MM], ssum = 0.f;
#pragma unroll
    for (int m = 0; m < MM; ++m) { w[m] = expf(rf[m] - mx); ssum += w[m]; }
    float inv = 1.f / ssum;
#pragma unroll
    for (int m = 0; m < MM; ++m) w[m] *= inv;

    // weighted = sum_m w[m] * vf[b,m,p,:]
#pragma unroll
    for (int c = 0; c < VDD / 32; ++c) {
        int d = lane + 32 * c;
        float accv = 0.f;
#pragma unroll
        for (int m = 0; m < MM; ++m)
            accv = fmaf(w[m], vf[(((size_t)b * MM + m) * NPTS + p) * VDD + d], accv);
        weighted[(size_t)g * VDD + d] = accv;
    }
}

// =====================================================================
// Launch
// =====================================================================
extern "C" void kernel_launch(void* const* d_in, const int* in_sizes, int n_in,
                              void* d_out, int out_size)
{
    (void)in_sizes; (void)n_in; (void)out_size;
    const float* pf   = (const float*)d_in[0];
    const float* vf   = (const float*)d_in[1];
    const int*   spid = (const int*)  d_in[2];
    const float* pW  = (const float*)d_in[3];
    const float* pb  = (const float*)d_in[4];
    const float* pg  = (const float*)d_in[5];
    const float* pbe = (const float*)d_in[6];
    const float* vW  = (const float*)d_in[7];
    const float* vb  = (const float*)d_in[8];
    const float* vg  = (const float*)d_in[9];
    const float* vbe = (const float*)d_in[10];
    const float* a1W = (const float*)d_in[11];
    const float* a1b = (const float*)d_in[12];
    const float* ag  = (const float*)d_in[13];
    const float* abe = (const float*)d_in[14];
    const float* a2W = (const float*)d_in[15];
    const float* a2b = (const float*)d_in[16];
    const float* fW  = (const float*)d_in[17];
    const float* fb  = (const float*)d_in[18];
    const float* fg  = (const float*)d_in[19];
    const float* fbe = (const float*)d_in[20];

    float *pp, *attn, *fmean, *amean, *wtd, *wvp;
    cudaGetSymbolAddress((void**)&pp,    g_pp);
    cudaGetSymbolAddress((void**)&attn,  g_attn);
    cudaGetSymbolAddress((void**)&fmean, g_fmean);
    cudaGetSymbolAddress((void**)&amean, g_amean);
    cudaGetSymbolAddress((void**)&wtd,   g_weighted);
    cudaGetSymbolAddress((void**)&wvp,   g_wvp);

    // dynamic smem sizes (floats): Wt + Xt + buf + 2*TR stats
    constexpr int SM256 = (16*256 + 16*66 + 64*256 + 2*64) * 4;   // 86.7 KB
    constexpr int SM512 = (8*512 + 8*34 + 32*512 + 2*32) * 4;     // 83.3 KB
    constexpr int SMATT = (16*256 + 16*66 + 64*256 + 2*64) * 4;   // 86.7 KB

    auto g256 = gemm_ln_k<256, 0, 256, 64, 16, true>;
    auto g512 = gemm_ln_k<256, 256, 512, 32, 8, false>;
    cudaFuncSetAttribute(g256, cudaFuncAttributeMaxDynamicSharedMemorySize, SM256);
    cudaFuncSetAttribute(g512, cudaFuncAttributeMaxDynamicSharedMemorySize, SM512);
    cudaFuncSetAttribute(attn_fused_k, cudaFuncAttributeMaxDynamicSharedMemorySize, SMATT);

    // 1) pp = relu(LN(pf @ pW + pb))
    g256<<<BNP / 64, 256, SM256>>>(pf, nullptr, pW, pb, pg, pbe, pp);

    // 2) fused vp/h/attn
    attn_fused_k<<<dim3(NPTS / 64, BB * MM), 256, SMATT>>>(
        vf, pp, vW, vb, vg, vbe, a1W, a1b, ag, abe, a2W, a2b, attn);

    // 3) segment means
    seg_stats_k<<<NSEG, 256>>>(spid, pp, attn, fmean, amean);

    // 4) refine + softmax + weighted view sum
    refine_weighted_k<<<BNP / 8, 256>>>(spid, pp, attn, vf, fmean, amean, wtd);

    // 5) wvp = relu(LN(weighted @ vW + vb))
    g256<<<BNP / 64, 256, SM256>>>(wtd, nullptr, vW, vb, vg, vbe, wvp);

    // 6) Z = LN([pp, wvp] @ fW + fb)
    g512<<<BNP / 32, 256, SM512>>>(pp, wvp, fW, fb, fg, fbe, (float*)d_out);
}

// round 7
// speedup vs baseline: 2.8145x; 1.3282x over previous
#include <cuda_runtime.h>
#include <cuda_bf16.h>
#include <mma.h>
#include <math.h>
#include <stdint.h>

using namespace nvcuda;
typedef unsigned int uint32;

// ---------------- problem dims ----------------
#define BB    4
#define MM    8
#define NPTS  4096
#define PDD   256
#define VDD   256
#define HH    256
#define FDD   512
#define SSEG  128
#define BNP   (BB*NPTS)              // 16384
#define NSEG  (BB*SSEG)              // 512
#define NRV   (BB*MM*NPTS)           // 131072

// ---------------- device scratch (no allocation allowed) ----------------
__device__ float g_pp[BNP*HH];
__device__ __nv_bfloat16 g_pp_h[BNP*HH], g_pp_l[BNP*HH];
__device__ __nv_bfloat16 g_vp_h[NRV*HH], g_vp_l[NRV*HH];
__device__ __nv_bfloat16 g_wvp_h[BNP*HH], g_wvp_l[BNP*HH];
__device__ float g_attn[NRV];
__device__ float g_fmean[NSEG*HH];
__device__ float g_amean[NSEG*MM];
__device__ float g_weighted[BNP*VDD];
// transposed+split weights: [N][K]
__device__ __nv_bfloat16 g_wp_h[HH*PDD],  g_wp_l[HH*PDD];
__device__ __nv_bfloat16 g_wv_h[HH*VDD],  g_wv_l[HH*VDD];
__device__ __nv_bfloat16 g_wa_h[HH*2*HH], g_wa_l[HH*2*HH];     // [256][512]
__device__ __nv_bfloat16 g_wf_h[FDD*2*HH], g_wf_l[FDD*2*HH];   // [512][512]

// =====================================================================
// Weight prep: W[K][N] fp32 -> W_t[N][K] split bf16 hi/lo
// =====================================================================
__global__ void prep_w(const float* __restrict__ W, int K, int N,
                       __nv_bfloat16* __restrict__ oh, __nv_bfloat16* __restrict__ ol) {
    int i = blockIdx.x * 256 + threadIdx.x;
    if (i >= N * K) return;
    int n = i / K, k = i % K;
    float v = W[(size_t)k * N + n];
    __nv_bfloat16 h = __float2bfloat16(v);
    oh[i] = h;
    ol[i] = __float2bfloat16(v - __bfloat162float(h));
}

// =====================================================================
// wmma split-bf16 GEMM + bias + LayerNorm epilogue.
// D = act(LN(concat(A0,A1) @ B^T + bias)), B planes are [N][KTOT].
// 8 warps: NW_N = N/64 warps across N, NW_M = 8/NW_N across M.
// Warp tile 32x64 (2x4 wmma 16x16 frags). M_tile = NW_M*32.
// 3-pass split: Ah*Bh + Ah*Bl + Al*Bh into fp32 accum.
// OUTMODE: 1=f32, 2=bf16 hi/lo planes, 3=both, 4=attn scalar
// =====================================================================
template<int N, int KTOT, int KC, bool RELU, int OUTMODE, bool A0F32, bool K2BMAP>
__global__ __launch_bounds__(256, 1) void tc_gemm_ln(
    const float* __restrict__ A0f,
    const __nv_bfloat16* __restrict__ A0h, const __nv_bfloat16* __restrict__ A0l, int ldA0,
    int ksplit,
    const __nv_bfloat16* __restrict__ A1h, const __nv_bfloat16* __restrict__ A1l, int ldA1,
    const __nv_bfloat16* __restrict__ Bh,  const __nv_bfloat16* __restrict__ Bl,
    const float* __restrict__ bias, const float* __restrict__ gamma, const float* __restrict__ beta,
    const float* __restrict__ a2W, const float* __restrict__ a2b,
    float* __restrict__ out_f, __nv_bfloat16* __restrict__ out_h, __nv_bfloat16* __restrict__ out_l)
{
    constexpr int LD   = KC + 8;                 // padded lead dim (conflict-free, 16B-aligned)
    constexpr int NW_N = N / 64;
    constexpr int NW_M = 8 / NW_N;
    constexpr int MT   = NW_M * 32;              // rows per block
    constexpr int ASZ  = MT * LD * 2;            // bytes per A plane
    constexpr int BSZ  = N * LD * 2;             // bytes per B plane
    constexpr int NCH  = KTOT / KC;
    constexpr int KS   = KC / 16;

    extern __shared__ char smem[];
    __nv_bfloat16* aH = (__nv_bfloat16*)(smem);
    __nv_bfloat16* aL = (__nv_bfloat16*)(smem + ASZ);
    __nv_bfloat16* bH = (__nv_bfloat16*)(smem + 2 * ASZ);
    __nv_bfloat16* bL = (__nv_bfloat16*)(smem + 2 * ASZ + BSZ);
    float*         buf = (float*)(smem + 2 * ASZ + 2 * BSZ);

    const int tid = threadIdx.x, wid = tid >> 5, lane = tid & 31;
    const int warpN = wid % NW_N, warpM = wid / NW_N;
    const int m0w = warpM * 32, n0w = warpN * 64;

    int rowA0base, rowA1base, outrow0;
    if (K2BMAP) {
        const int bm = blockIdx.y;
        const int b  = bm >> 3;
        rowA0base = b  * NPTS + blockIdx.x * MT;
        rowA1base = bm * NPTS + blockIdx.x * MT;
        outrow0   = bm * NPTS + blockIdx.x * MT;
    } else {
        rowA0base = rowA1base = outrow0 = blockIdx.x * MT;
    }

    wmma::fragment<wmma::accumulator, 16, 16, 16, float> acc[2][4];
#pragma unroll
    for (int mi = 0; mi < 2; ++mi)
#pragma unroll
        for (int ni = 0; ni < 4; ++ni) wmma::fill_fragment(acc[mi][ni], 0.f);

    for (int ch = 0; ch < NCH; ++ch) {
        const int k0 = ch * KC;
        const bool useA1 = (k0 >= ksplit);
        // ---------- stage A ----------
        {
            constexpr int CH = KC / 8;
            if (A0F32) {
                for (int idx = tid; idx < MT * CH; idx += 256) {
                    int m = idx / CH, c = idx % CH;
                    const float* src = A0f + (size_t)(rowA0base + m) * ldA0 + k0 + c * 8;
                    float4 v0 = ((const float4*)src)[0];
                    float4 v1 = ((const float4*)src)[1];
                    __nv_bfloat162 h0 = __floats2bfloat162_rn(v0.x, v0.y);
                    __nv_bfloat162 h1 = __floats2bfloat162_rn(v0.z, v0.w);
                    __nv_bfloat162 h2 = __floats2bfloat162_rn(v1.x, v1.y);
                    __nv_bfloat162 h3 = __floats2bfloat162_rn(v1.z, v1.w);
                    __nv_bfloat162 l0 = __floats2bfloat162_rn(v0.x - __low2float(h0), v0.y - __high2float(h0));
                    __nv_bfloat162 l1 = __floats2bfloat162_rn(v0.z - __low2float(h1), v0.w - __high2float(h1));
                    __nv_bfloat162 l2 = __floats2bfloat162_rn(v1.x - __low2float(h2), v1.y - __high2float(h2));
                    __nv_bfloat162 l3 = __floats2bfloat162_rn(v1.z - __low2float(h3), v1.w - __high2float(h3));
                    uint4 uh = make_uint4(*(uint32*)&h0, *(uint32*)&h1, *(uint32*)&h2, *(uint32*)&h3);
                    uint4 ul = make_uint4(*(uint32*)&l0, *(uint32*)&l1, *(uint32*)&l2, *(uint32*)&l3);
                    *(uint4*)(aH + m * LD + c * 8) = uh;
                    *(uint4*)(aL + m * LD + c * 8) = ul;
                }
            } else {
                const __nv_bfloat16* sh = useA1 ? A1h : A0h;
                const __nv_bfloat16* sl = useA1 ? A1l : A0l;
                const int rb = useA1 ? rowA1base : rowA0base;
                const int ld = useA1 ? ldA1 : ldA0;
                const int kb = useA1 ? (k0 - ksplit) : k0;
                for (int idx = tid; idx < MT * CH; idx += 256) {
                    int m = idx / CH, c = idx % CH;
                    *(uint4*)(aH + m * LD + c * 8) =
                        *(const uint4*)(sh + (size_t)(rb + m) * ld + kb + c * 8);
                    *(uint4*)(aL + m * LD + c * 8) =
                        *(const uint4*)(sl + (size_t)(rb + m) * ld + kb + c * 8);
                }
            }
        }
        // ---------- stage B ----------
        {
            constexpr int CH = KC / 8;
            for (int idx = tid; idx < N * CH; idx += 256) {
                int n = idx / CH, c = idx % CH;
                *(uint4*)(bH + n * LD + c * 8) =
                    *(const uint4*)(Bh + (size_t)n * KTOT + k0 + c * 8);
                *(uint4*)(bL + n * LD + c * 8) =
                    *(const uint4*)(Bl + (size_t)n * KTOT + k0 + c * 8);
            }
        }
        __syncthreads();
        // ---------- compute ----------
#pragma unroll
        for (int ks = 0; ks < KS; ++ks) {
            const int kk = ks * 16;
            wmma::fragment<wmma::matrix_a, 16, 16, 16, __nv_bfloat16, wmma::row_major> ah[2], al[2];
#pragma unroll
            for (int mi = 0; mi < 2; ++mi) {
                wmma::load_matrix_sync(ah[mi], aH + (m0w + mi * 16) * LD + kk, LD);
                wmma::load_matrix_sync(al[mi], aL + (m0w + mi * 16) * LD + kk, LD);
            }
#pragma unroll
            for (int ni = 0; ni < 4; ++ni) {
                wmma::fragment<wmma::matrix_b, 16, 16, 16, __nv_bfloat16, wmma::col_major> bh, bl;
                wmma::load_matrix_sync(bh, bH + (n0w + ni * 16) * LD + kk, LD);
                wmma::load_matrix_sync(bl, bL + (n0w + ni * 16) * LD + kk, LD);
#pragma unroll
                for (int mi = 0; mi < 2; ++mi) {
                    wmma::mma_sync(acc[mi][ni], ah[mi], bh, acc[mi][ni]);
                    wmma::mma_sync(acc[mi][ni], ah[mi], bl, acc[mi][ni]);
                    wmma::mma_sync(acc[mi][ni], al[mi], bh, acc[mi][ni]);
                }
            }
        }
        __syncthreads();
    }

    // ---------- store accumulators to buf ----------
#pragma unroll
    for (int mi = 0; mi < 2; ++mi)
#pragma unroll
        for (int ni = 0; ni < 4; ++ni)
            wmma::store_matrix_sync(buf + (size_t)(m0w + mi * 16) * N + n0w + ni * 16,
                                    acc[mi][ni], N, wmma::mem_row_major);
    __syncthreads();

    // ---------- LN epilogue: warp per row ----------
    for (int r = wid; r < MT; r += 8) {
        const int orow = outrow0 + r;
        float s = 0.f, sq = 0.f;
        for (int j = lane; j < N; j += 32) {
            float v = buf[(size_t)r * N + j] + bias[j];
            s += v; sq += v * v;
        }
#pragma unroll
        for (int o = 16; o > 0; o >>= 1) {
            s  += __shfl_xor_sync(0xffffffffu, s,  o);
            sq += __shfl_xor_sync(0xffffffffu, sq, o);
        }
        const float mu = s / (float)N;
        const float rs = rsqrtf(sq / (float)N - mu * mu + 1e-5f);
        if (OUTMODE == 4) {
            float dot = 0.f;
            for (int j = lane; j < N; j += 32) {
                float v = (buf[(size_t)r * N + j] + bias[j] - mu) * rs * gamma[j] + beta[j];
                v = fmaxf(v, 0.f);
                dot = fmaf(v, a2W[j], dot);
            }
#pragma unroll
            for (int o = 16; o > 0; o >>= 1) dot += __shfl_xor_sync(0xffffffffu, dot, o);
            if (lane == 0)
                out_f[orow] = 1.f / (1.f + expf(-(dot + a2b[0])));
        } else {
            for (int j = lane; j < N; j += 32) {
                float v = (buf[(size_t)r * N + j] + bias[j] - mu) * rs * gamma[j] + beta[j];
                if (RELU) v = fmaxf(v, 0.f);
                if (OUTMODE & 1)
                    out_f[(size_t)orow * N + j] = v;
                if (OUTMODE & 2) {
                    __nv_bfloat16 h = __float2bfloat16(v);
                    out_h[(size_t)orow * N + j] = h;
                    out_l[(size_t)orow * N + j] = __float2bfloat16(v - __bfloat162float(h));
                }
            }
        }
    }
}

// =====================================================================
// Segment means: one block per (b, s). Deterministic (no atomics).
// =====================================================================
__global__ __launch_bounds__(256) void seg_stats_k(
    const int* __restrict__ sp, const float* __restrict__ pp_,
    const float* __restrict__ attn,
    float* __restrict__ fmean, float* __restrict__ amean)
{
    __shared__ int sids[NPTS];
    const int b = blockIdx.x / SSEG, s = blockIdx.x % SSEG;
    const int tid = threadIdx.x;
    for (int i = tid; i < NPTS; i += 256) sids[i] = sp[b * NPTS + i];
    __syncthreads();

    float facc = 0.f, aacc = 0.f;
    int cnt = 0;
    for (int p = 0; p < NPTS; ++p) {
        if (sids[p] == s) {
            facc += pp_[((size_t)b * NPTS + p) * HH + tid];
            if (tid < MM) aacc += attn[((size_t)b * MM + tid) * NPTS + p];
            ++cnt;
        }
    }
    float inv = 1.f / (float)(cnt > 0 ? cnt : 1);
    fmean[(size_t)blockIdx.x * HH + tid] = facc * inv;
    if (tid < MM) amean[blockIdx.x * MM + tid] = aacc * inv;
}

// =====================================================================
// Refine + softmax(8 views) + weighted view-feature sum. One warp/point.
// =====================================================================
__global__ __launch_bounds__(256) void refine_weighted_k(
    const int* __restrict__ sp, const float* __restrict__ pp_,
    const float* __restrict__ attn, const float* __restrict__ vf,
    const float* __restrict__ fmean, const float* __restrict__ amean,
    float* __restrict__ weighted)
{
    const int wid = threadIdx.x >> 5, lane = threadIdx.x & 31;
    const int g = blockIdx.x * 8 + wid;
    const int b = g / NPTS, p = g % NPTS;

    const int s = sp[g];
    float a[MM], rf[MM];
#pragma unroll
    for (int m = 0; m < MM; ++m) a[m] = attn[((size_t)b * MM + m) * NPTS + p];

    if (s >= 0) {
        const int seg = b * SSEG + s;
        const float* f  = pp_   + (size_t)g   * HH;
        const float* fm = fmean + (size_t)seg * HH;
        float dot = 0.f, nf = 0.f, nm = 0.f;
        for (int j = lane; j < HH; j += 32) {
            float x = f[j], y = fm[j];
            dot = fmaf(x, y, dot); nf = fmaf(x, x, nf); nm = fmaf(y, y, nm);
        }
#pragma unroll
        for (int o = 16; o > 0; o >>= 1) {
            dot += __shfl_xor_sync(0xffffffffu, dot, o);
            nf  += __shfl_xor_sync(0xffffffffu, nf,  o);
            nm  += __shfl_xor_sync(0xffffffffu, nm,  o);
        }
        float sim = dot / (fmaxf(sqrtf(nf), 1e-8f) * fmaxf(sqrtf(nm), 1e-8f));
#pragma unroll
        for (int m = 0; m < MM; ++m) {
            float am = amean[seg * MM + m];
            rf[m] = am + (a[m] - am) * sim;
        }
    } else {
#pragma unroll
        for (int m = 0; m < MM; ++m) rf[m] = a[m];
    }

    float mx = rf[0];
#pragma unroll
    for (int m = 1; m < MM; ++m) mx = fmaxf(mx, rf[m]);
    float w[MM], ssum = 0.f;
#pragma unroll
    for (int m = 0; m < MM; ++m) { w[m] = expf(rf[m] - mx); ssum += w[m]; }
    float inv = 1.f / ssum;
#pragma unroll
    for (int m = 0; m < MM; ++m) w[m] *= inv;

#pragma unroll
    for (int c = 0; c < VDD / 32; ++c) {
        int d = lane + 32 * c;
        float accv = 0.f;
#pragma unroll
        for (int m = 0; m < MM; ++m)
            accv = fmaf(w[m], vf[(((size_t)b * MM + m) * NPTS + p) * VDD + d], accv);
        weighted[(size_t)g * VDD + d] = accv;
    }
}

// =====================================================================
// Launch
// =====================================================================
extern "C" void kernel_launch(void* const* d_in, const int* in_sizes, int n_in,
                              void* d_out, int out_size)
{
    (void)in_sizes; (void)n_in; (void)out_size;
    const float* pf   = (const float*)d_in[0];
    const float* vf   = (const float*)d_in[1];
    const int*   spid = (const int*)  d_in[2];
    const float* pW  = (const float*)d_in[3];
    const float* pb  = (const float*)d_in[4];
    const float* pg  = (const float*)d_in[5];
    const float* pbe = (const float*)d_in[6];
    const float* vW  = (const float*)d_in[7];
    const float* vb  = (const float*)d_in[8];
    const float* vg  = (const float*)d_in[9];
    const float* vbe = (const float*)d_in[10];
    const float* a1W = (const float*)d_in[11];
    const float* a1b = (const float*)d_in[12];
    const float* ag  = (const float*)d_in[13];
    const float* abe = (const float*)d_in[14];
    const float* a2W = (const float*)d_in[15];
    const float* a2b = (const float*)d_in[16];
    const float* fW  = (const float*)d_in[17];
    const float* fb  = (const float*)d_in[18];
    const float* fg  = (const float*)d_in[19];
    const float* fbe = (const float*)d_in[20];

    float *pp, *attn, *fmean, *amean, *wtd;
    __nv_bfloat16 *pp_h, *pp_l, *vp_h, *vp_l, *wvp_h, *wvp_l;
    __nv_bfloat16 *wp_h, *wp_l, *wv_h, *wv_l, *wa_h, *wa_l, *wf_h, *wf_l;
    cudaGetSymbolAddress((void**)&pp,    g_pp);
    cudaGetSymbolAddress((void**)&attn,  g_attn);
    cudaGetSymbolAddress((void**)&fmean, g_fmean);
    cudaGetSymbolAddress((void**)&amean, g_amean);
    cudaGetSymbolAddress((void**)&wtd,   g_weighted);
    cudaGetSymbolAddress((void**)&pp_h,  g_pp_h);  cudaGetSymbolAddress((void**)&pp_l,  g_pp_l);
    cudaGetSymbolAddress((void**)&vp_h,  g_vp_h);  cudaGetSymbolAddress((void**)&vp_l,  g_vp_l);
    cudaGetSymbolAddress((void**)&wvp_h, g_wvp_h); cudaGetSymbolAddress((void**)&wvp_l, g_wvp_l);
    cudaGetSymbolAddress((void**)&wp_h,  g_wp_h);  cudaGetSymbolAddress((void**)&wp_l,  g_wp_l);
    cudaGetSymbolAddress((void**)&wv_h,  g_wv_h);  cudaGetSymbolAddress((void**)&wv_l,  g_wv_l);
    cudaGetSymbolAddress((void**)&wa_h,  g_wa_h);  cudaGetSymbolAddress((void**)&wa_l,  g_wa_l);
    cudaGetSymbolAddress((void**)&wf_h,  g_wf_h);  cudaGetSymbolAddress((void**)&wf_l,  g_wf_l);

    // smem: 2*ASZ + 2*BSZ + MT*N*4
    constexpr int SM256 = 2 * (64 * 72 * 2) + 2 * (256 * 72 * 2) + 64 * 256 * 4;  // 157696
    constexpr int SM512 = 2 * (32 * 40 * 2) + 2 * (512 * 40 * 2) + 32 * 512 * 4;  // 152576

    auto kK1  = tc_gemm_ln<256, 256, 64, true,  3, true,  false>;
    auto kGEN = tc_gemm_ln<256, 256, 64, true,  2, true,  false>;
    auto kATT = tc_gemm_ln<256, 512, 64, true,  4, false, true >;
    auto kFIN = tc_gemm_ln<512, 512, 32, false, 1, false, false>;
    cudaFuncSetAttribute(kK1,  cudaFuncAttributeMaxDynamicSharedMemorySize, SM256);
    cudaFuncSetAttribute(kGEN, cudaFuncAttributeMaxDynamicSharedMemorySize, SM256);
    cudaFuncSetAttribute(kATT, cudaFuncAttributeMaxDynamicSharedMemorySize, SM256);
    cudaFuncSetAttribute(kFIN, cudaFuncAttributeMaxDynamicSharedMemorySize, SM512);

    // 0) weight prep: transpose + split
    prep_w<<<(HH * PDD + 255) / 256, 256>>>(pW, PDD, HH, wp_h, wp_l);
    prep_w<<<(HH * VDD + 255) / 256, 256>>>(vW, VDD, HH, wv_h, wv_l);
    prep_w<<<(HH * 2 * HH + 255) / 256, 256>>>(a1W, 2 * HH, HH, wa_h, wa_l);
    prep_w<<<(FDD * 2 * HH + 255) / 256, 256>>>(fW, 2 * HH, FDD, wf_h, wf_l);

    // 1) pp = relu(LN(pf @ pW + pb)) -> fp32 + bf16 planes
    kK1<<<BNP / 64, 256, SM256>>>(pf, nullptr, nullptr, PDD, PDD,
        nullptr, nullptr, 0, wp_h, wp_l, pb, pg, pbe, nullptr, nullptr,
        pp, pp_h, pp_l);

    // 2a) vp = relu(LN(vf @ vW + vb)) -> bf16 planes
    kGEN<<<NRV / 64, 256, SM256>>>(vf, nullptr, nullptr, VDD, VDD,
        nullptr, nullptr, 0, wv_h, wv_l, vb, vg, vbe, nullptr, nullptr,
        nullptr, vp_h, vp_l);

    // 2b) attn = sigmoid(relu(LN([pp, vp] @ a1W + a1b)) . a2W + a2b)
    kATT<<<dim3(NPTS / 64, BB * MM), 256, SM256>>>(nullptr, pp_h, pp_l, HH, HH,
        vp_h, vp_l, HH, wa_h, wa_l, a1b, ag, abe, a2W, a2b,
        attn, nullptr, nullptr);

    // 3) segment means
    seg_stats_k<<<NSEG, 256>>>(spid, pp, attn, fmean, amean);

    // 4) refine + softmax + weighted view sum
    refine_weighted_k<<<BNP / 8, 256>>>(spid, pp, attn, vf, fmean, amean, wtd);

    // 5) wvp = relu(LN(weighted @ vW + vb)) -> bf16 planes
    kGEN<<<BNP / 64, 256, SM256>>>(wtd, nullptr, nullptr, VDD, VDD,
        nullptr, nullptr, 0, wv_h, wv_l, vb, vg, vbe, nullptr, nullptr,
        nullptr, wvp_h, wvp_l);

    // 6) Z = LN([pp, wvp] @ fW + fb) -> d_out
    kFIN<<<BNP / 32, 256, SM512>>>(nullptr, pp_h, pp_l, HH, HH,
        wvp_h, wvp_l, HH, wf_h, wf_l, fb, fg, fbe, nullptr, nullptr,
        (float*)d_out, nullptr, nullptr);
}